// round 6
// baseline (speedup 1.0000x reference)
#include <cuda_runtime.h>
#include <cuda_fp16.h>

// KalmanNetNN: sequential 100-step Kalman/GRU scan, persistent kernel.
// Round 5 = Round 4 resubmit (infra failure, never measured):
// half-row dot units (4x LDG.128, MLP=4), SoA 2-partials per row,
// cheap coalesced combines, transposed-W3 epilogue, uniform K-stride 2048.

#define M10   10
#define NTT   100
#define H1D   1600
#define H2D   400
#define HID   2000
#define G3D   6000
#define DIN   30
#define SW    2048            // uniform padded K stride (halves / floats)

// ---------------- device scratch (static; no allocations allowed) ----------
__device__ __half Wh0h[G3D * SW];
__device__ __half Wh1h[G3D * SW];
__device__ __half Wi1h[G3D * SW];
__device__ __half Wi0h[G3D * SW];
__device__ __half W2h [H2D * SW];
__device__ float  g_W3t[H2D * 128];        // W3 transposed: [j][r], r padded to 128

// partial sums, SoA: [part(2)][3H rows]
__device__ float g_ph0[2 * G3D];
__device__ float g_ph1[2 * G3D];
__device__ float g_pi0[2 * G3D];
__device__ float g_pi1[2 * G3D];
__device__ float g_pw2[2 * H2D];
__device__ float g_a[H1D];
__device__ float g_post[M10], g_prev_post[M10], g_prev_prior[M10], g_yprev[M10];
__device__ float g_h1i[HID], g_h2i[HID];
__device__ unsigned g_bar;
__device__ unsigned g_epoch;

// ---------------- helpers ---------------------------------------------------
__device__ __forceinline__ float sigmoidf_(float x) {
    return 1.0f / (1.0f + expf(-x));
}
__device__ __forceinline__ float tanhf_(float x) {
    x = fminf(fmaxf(x, -15.0f), 15.0f);
    float e = expf(2.0f * x);
    return (e - 1.0f) / (e + 1.0f);
}
__device__ __forceinline__ float warp_sum(float x) {
#pragma unroll
    for (int o = 16; o; o >>= 1) x += __shfl_xor_sync(0xffffffffu, x, o);
    return x;
}

// half-row dot: 1024 halves of one row (half index hf) vs fp32 smem vector.
// lane covers 4 x 8 contiguous halves (one uint4 per 256-half segment).
__device__ __forceinline__ float halfrow_dot(const __half* __restrict__ wmat,
                                             int row, int hf,
                                             const float* __restrict__ v,
                                             int lane) {
    const __half* p = wmat + (size_t)row * SW + hf * 1024;
    const float*  q = v + hf * 1024;
    float s = 0.0f;
#pragma unroll
    for (int k = 0; k < 4; k++) {
        int off = k * 256 + lane * 8;
        uint4 wv = *reinterpret_cast<const uint4*>(p + off);
        float4 a0 = *reinterpret_cast<const float4*>(q + off);
        float4 a1 = *reinterpret_cast<const float4*>(q + off + 4);
        const __half2* hp = reinterpret_cast<const __half2*>(&wv);
        float2 f0 = __half22float2(hp[0]);
        float2 f1 = __half22float2(hp[1]);
        float2 f2 = __half22float2(hp[2]);
        float2 f3 = __half22float2(hp[3]);
        s = fmaf(f0.x, a0.x, s); s = fmaf(f0.y, a0.y, s);
        s = fmaf(f1.x, a0.z, s); s = fmaf(f1.y, a0.w, s);
        s = fmaf(f2.x, a1.x, s); s = fmaf(f2.y, a1.y, s);
        s = fmaf(f3.x, a1.z, s); s = fmaf(f3.y, a1.w, s);
    }
#pragma unroll
    for (int o = 16; o; o >>= 1) s += __shfl_xor_sync(0xffffffffu, s, o);
    return s;
}

// grid barrier: arrive + poll monotonic counter (reset by prep kernel)
__device__ __forceinline__ void gsync(unsigned target) {
    __syncthreads();
    if (threadIdx.x == 0) {
        __threadfence();
        atomicAdd(&g_bar, 1u);
        while (*(volatile unsigned*)&g_bar < target) { }
        __threadfence();
    }
    __syncthreads();
}

// ---------------- prep kernel: fp16 convert + W3 transpose + state init ----
__global__ void knet_prep(const float* __restrict__ Wi0,
                          const float* __restrict__ Wh0,
                          const float* __restrict__ Wi1,
                          const float* __restrict__ Wh1,
                          const float* __restrict__ W2,
                          const float* __restrict__ W3,
                          const float* __restrict__ m1x0,
                          const float* __restrict__ F,
                          const float* __restrict__ Hm,
                          const float* __restrict__ h0) {
    const int which = blockIdx.y;
    const unsigned stride = gridDim.x * blockDim.x;
    const unsigned t0 = blockIdx.x * blockDim.x + threadIdx.x;
    if (which < 4) {
        const float* src = (which == 0) ? Wh0 : (which == 1) ? Wh1
                         : (which == 2) ? Wi1 : Wi0;
        __half* dst = (which == 0) ? Wh0h : (which == 1) ? Wh1h
                    : (which == 2) ? Wi1h : Wi0h;
        const int srcK = (which == 3) ? H1D : HID;
        const unsigned n = G3D * SW;
        for (unsigned i = t0; i < n; i += stride) {
            unsigned col = i & (SW - 1);
            unsigned row = i >> 11;
            float v = (col < (unsigned)srcK) ? src[row * srcK + col] : 0.0f;
            dst[i] = __float2half_rn(v);
        }
    } else if (which == 4) {
        const unsigned n = H2D * SW;
        for (unsigned i = t0; i < n; i += stride) {
            unsigned col = i & (SW - 1);
            unsigned row = i >> 11;
            float v = (col < HID) ? W2[row * HID + col] : 0.0f;
            W2h[i] = __float2half_rn(v);
        }
        // W3 transpose: g_W3t[j*128 + r] = W3[r*H2D + j], r<100
        const unsigned n3 = H2D * 128;
        for (unsigned i = t0; i < n3; i += stride) {
            unsigned j = i >> 7;
            unsigned r = i & 127;
            g_W3t[i] = (r < 100) ? W3[r * H2D + j] : 0.0f;
        }
    } else if (blockIdx.x == 0) {
        int t = threadIdx.x;
        __shared__ float fm[M10];
        if (t == 0) { g_bar = 0u; g_epoch = 0u; }
        if (t < M10) {
            float s = 0.0f;
            for (int j = 0; j < M10; j++) s = fmaf(F[t * M10 + j], m1x0[j], s);
            fm[t] = s;
            g_post[t] = m1x0[t];
            g_prev_post[t] = 0.0f;
            g_prev_prior[t] = m1x0[t];
        }
        __syncthreads();
        if (t < M10) {
            float s = 0.0f;
            for (int j = 0; j < M10; j++) s = fmaf(Hm[t * M10 + j], fm[j], s);
            g_yprev[t] = s;
        }
        for (int i = t; i < HID; i += blockDim.x) {
            g_h1i[i] = h0[i];
            g_h2i[i] = h0[HID + i];
        }
    }
}

// ---------------- epilogue of step te (one warp: CTA0/warp0) ---------------
__device__ __forceinline__ void epilogue(int te, int lane,
                                         const float* __restrict__ y,
                                         const float* __restrict__ F,
                                         const float* __restrict__ Hm,
                                         const float* __restrict__ b3,
                                         const float* __restrict__ b2,
                                         float* __restrict__ out,
                                         float* s_scr) {
    float* s_g  = s_scr;        // 400
    float* s_kg = s_scr + 400;  // 100
    float* s_pr = s_scr + 512;  // 10
    float* s_dy = s_scr + 528;  // 10

    // g = relu(part0+part1 + b2) -- coalesced SoA reads
    for (int i = lane; i < H2D; i += 32) {
        s_g[i] = fmaxf(b2[i] + g_pw2[i] + g_pw2[H2D + i], 0.0f);
    }
    __syncwarp();
    // KG = W3 @ g + b3 using transposed W3 (coalesced: lane = row)
    {
        float acc0 = 0.0f, acc1 = 0.0f, acc2 = 0.0f, acc3 = 0.0f;
        for (int j = 0; j < H2D; j++) {
            float gv = s_g[j];
            const float* col = g_W3t + j * 128;
            acc0 = fmaf(col[lane],      gv, acc0);
            acc1 = fmaf(col[lane + 32], gv, acc1);
            acc2 = fmaf(col[lane + 64], gv, acc2);
            if (lane < 4) acc3 = fmaf(col[lane + 96], gv, acc3);
        }
        s_kg[lane]      = acc0 + b3[lane];
        s_kg[lane + 32] = acc1 + b3[lane + 32];
        s_kg[lane + 64] = acc2 + b3[lane + 64];
        if (lane < 4) s_kg[lane + 96] = acc3 + b3[lane + 96];
    }
    __syncwarp();
    if (lane < M10) {
        float s = 0.0f;
        for (int j = 0; j < M10; j++) s = fmaf(F[lane * M10 + j], g_post[j], s);
        s_pr[lane] = s;
    }
    __syncwarp();
    if (lane < M10) {
        float m1y = 0.0f;
        for (int j = 0; j < M10; j++) m1y = fmaf(Hm[lane * M10 + j], s_pr[j], m1y);
        s_dy[lane] = y[lane * NTT + te] - m1y;
    }
    __syncwarp();
    if (lane < M10) {
        float np = s_pr[lane];
        for (int j = 0; j < M10; j++) np = fmaf(s_kg[lane * M10 + j], s_dy[j], np);
        g_prev_post[lane]  = g_post[lane];
        g_prev_prior[lane] = s_pr[lane];
        g_yprev[lane]      = y[lane * NTT + te];
        out[lane * NTT + te] = np;
        g_post[lane] = np;
    }
    __syncwarp();
}

// ---------------- main persistent kernel -----------------------------------
__global__ void __launch_bounds__(1024, 1)
knet_main(const float* __restrict__ y,
          const float* __restrict__ W1,  const float* __restrict__ b1,
          const float* __restrict__ bi0, const float* __restrict__ bh0,
          const float* __restrict__ bi1, const float* __restrict__ bh1,
          const float* __restrict__ b2,  const float* __restrict__ b3,
          const float* __restrict__ F,   const float* __restrict__ Hm,
          float* __restrict__ out) {
    __shared__ __align__(16) float s_h1[SW];
    __shared__ __align__(16) float s_h2[SW];
    __shared__ __align__(16) float s_a[SW];    // doubles as epilogue scratch
    __shared__ float s_kin[DIN];

    const int tid  = threadIdx.x;
    const int lane = tid & 31;
    const int wid  = tid >> 5;
    const unsigned gw = blockIdx.x * 32u + (unsigned)wid;
    const unsigned NW = gridDim.x * 32u;

    for (int i = tid; i < SW; i += 1024) {
        s_h1[i] = (i < HID) ? g_h1i[i] : 0.0f;
        s_h2[i] = (i < HID) ? g_h2i[i] : 0.0f;
        s_a[i]  = 0.0f;
    }
    __syncthreads();

    unsigned tgt = 0;

    for (int t = 0; t < NTT; ++t) {
        // ---- P1a: prev-step epilogue (CTA0.warp0) overlapped with
        //      gh0 = Wh0@h1, gh1 = Wh1@h2 : 24000 half-row units
        if (blockIdx.x == 0 && wid == 0 && t > 0) {
            epilogue(t - 1, lane, y, F, Hm, b3, b2, out, s_a);
            if (lane == 0) {
                __threadfence();
                *(volatile unsigned*)&g_epoch = (unsigned)t;
            }
            __syncwarp();
        }
        for (unsigned u = gw; u < 24000u; u += NW) {
            bool first = (u < 12000u);
            unsigned v = first ? u : (u - 12000u);
            int row = (int)(v >> 1);
            int hf  = (int)(v & 1u);
            float d = first ? halfrow_dot(Wh0h, row, hf, s_h1, lane)
                            : halfrow_dot(Wh1h, row, hf, s_h2, lane);
            if (lane == 0) {
                float* dst = first ? g_ph0 : g_ph1;
                dst[hf * G3D + row] = d;
            }
        }
        __syncthreads();

        // ---- P1b: wait for state update, compute normalized features
        if (wid == 0) {
            while (*(volatile unsigned*)&g_epoch < (unsigned)t) { }
            __threadfence();
            float yt = 0.0f, p = 0.0f, pp = 0.0f, ppr = 0.0f, yp = 0.0f;
            if (lane < M10) {
                yt  = y[lane * NTT + t];
                p   = g_post[lane];
                pp  = g_prev_post[lane];
                ppr = g_prev_prior[lane];
                yp  = g_yprev[lane];
            }
            float d1 = yt - yp;
            float d3 = p - pp;
            float d4 = p - ppr;
            float n1 = fmaxf(sqrtf(warp_sum(d1 * d1)), 1e-12f);
            float n3 = fmaxf(sqrtf(warp_sum(d3 * d3)), 1e-12f);
            float n4 = fmaxf(sqrtf(warp_sum(d4 * d4)), 1e-12f);
            if (lane < M10) {
                s_kin[lane]      = d1 / n1;
                s_kin[10 + lane] = d3 / n3;
                s_kin[20 + lane] = d4 / n4;
            }
        }
        __syncthreads();

        // ---- P1c: a = relu(W1 @ kin + b1)
        for (unsigned r = gw; r < (unsigned)H1D; r += NW) {
            float s = (lane < DIN) ? W1[r * DIN + lane] * s_kin[lane] : 0.0f;
            s = warp_sum(s);
            if (lane == 0) g_a[r] = fmaxf(s + b1[r], 0.0f);
        }
        tgt += gridDim.x; gsync(tgt);

        // ---- P2: stage a, then gi0 = Wi0 @ a : 12000 half-row units
        for (int i = tid; i < H1D; i += 1024) s_a[i] = g_a[i];
        __syncthreads();
        for (unsigned u = gw; u < 12000u; u += NW) {
            int row = (int)(u >> 1);
            int hf  = (int)(u & 1u);
            float d = halfrow_dot(Wi0h, row, hf, s_a, lane);
            if (lane == 0) g_pi0[hf * G3D + row] = d;
        }
        tgt += gridDim.x; gsync(tgt);

        // ---- P3: h1n combine (per-CTA, coalesced SoA) then gi1 = Wi1 @ h1n
        for (int j = tid; j < HID; j += 1024) {
            float ir = bi0[j]           + g_pi0[j]            + g_pi0[G3D + j];
            float iz = bi0[j + HID]     + g_pi0[HID + j]      + g_pi0[G3D + HID + j];
            float in = bi0[j + 2 * HID] + g_pi0[2 * HID + j]  + g_pi0[G3D + 2 * HID + j];
            float hr = bh0[j]           + g_ph0[j]            + g_ph0[G3D + j];
            float hz = bh0[j + HID]     + g_ph0[HID + j]      + g_ph0[G3D + HID + j];
            float hn = bh0[j + 2 * HID] + g_ph0[2 * HID + j]  + g_ph0[G3D + 2 * HID + j];
            float r  = sigmoidf_(ir + hr);
            float z  = sigmoidf_(iz + hz);
            float nn = tanhf_(in + r * hn);
            s_h1[j] = (1.0f - z) * nn + z * s_h1[j];
        }
        __syncthreads();
        for (unsigned u = gw; u < 12000u; u += NW) {
            int row = (int)(u >> 1);
            int hf  = (int)(u & 1u);
            float d = halfrow_dot(Wi1h, row, hf, s_h1, lane);
            if (lane == 0) g_pi1[hf * G3D + row] = d;
        }
        tgt += gridDim.x; gsync(tgt);

        // ---- P4: h2n combine then g partials = W2 @ h2n : 800 units
        for (int j = tid; j < HID; j += 1024) {
            float ir = bi1[j]           + g_pi1[j]            + g_pi1[G3D + j];
            float iz = bi1[j + HID]     + g_pi1[HID + j]      + g_pi1[G3D + HID + j];
            float in = bi1[j + 2 * HID] + g_pi1[2 * HID + j]  + g_pi1[G3D + 2 * HID + j];
            float hr = bh1[j]           + g_ph1[j]            + g_ph1[G3D + j];
            float hz = bh1[j + HID]     + g_ph1[HID + j]      + g_ph1[G3D + HID + j];
            float hn = bh1[j + 2 * HID] + g_ph1[2 * HID + j]  + g_ph1[G3D + 2 * HID + j];
            float r  = sigmoidf_(ir + hr);
            float z  = sigmoidf_(iz + hz);
            float nn = tanhf_(in + r * hn);
            s_h2[j] = (1.0f - z) * nn + z * s_h2[j];
        }
        __syncthreads();
        for (unsigned u = gw; u < 800u; u += NW) {
            int row = (int)(u >> 1);
            int hf  = (int)(u & 1u);
            float d = halfrow_dot(W2h, row, hf, s_h2, lane);
            if (lane == 0) g_pw2[hf * H2D + row] = d;
        }
        tgt += gridDim.x; gsync(tgt);
    }

    if (blockIdx.x == 0 && wid == 0) {
        epilogue(NTT - 1, lane, y, F, Hm, b3, b2, out, s_a);
    }
}

// ---------------- launcher --------------------------------------------------
extern "C" void kernel_launch(void* const* d_in, const int* in_sizes, int n_in,
                              void* d_out, int out_size) {
    (void)in_sizes; (void)n_in; (void)out_size;
    const float* y    = (const float*)d_in[0];
    const float* m1x0 = (const float*)d_in[1];
    const float* F    = (const float*)d_in[2];
    const float* Hm   = (const float*)d_in[3];
    const float* h0   = (const float*)d_in[4];
    const float* W1   = (const float*)d_in[5];
    const float* b1   = (const float*)d_in[6];
    const float* Wi0  = (const float*)d_in[7];
    const float* Wh0  = (const float*)d_in[8];
    const float* bi0  = (const float*)d_in[9];
    const float* bh0  = (const float*)d_in[10];
    const float* Wi1  = (const float*)d_in[11];
    const float* Wh1  = (const float*)d_in[12];
    const float* bi1  = (const float*)d_in[13];
    const float* bh1  = (const float*)d_in[14];
    const float* W2   = (const float*)d_in[15];
    const float* b2   = (const float*)d_in[16];
    const float* W3   = (const float*)d_in[17];
    const float* b3   = (const float*)d_in[18];
    float* out = (float*)d_out;

    int dev = 0;
    cudaGetDevice(&dev);
    int nsm = 148;
    cudaDeviceGetAttribute(&nsm, cudaDevAttrMultiProcessorCount, dev);

    knet_prep<<<dim3(2 * nsm, 6), 256>>>(Wi0, Wh0, Wi1, Wh1, W2, W3,
                                         m1x0, F, Hm, h0);
    knet_main<<<nsm, 1024>>>(y, W1, b1, bi0, bh0, bi1, bh1,
                             b2, b3, F, Hm, out);
}

// round 8
// speedup vs baseline: 1.3719x; 1.3719x over previous
#include <cuda_runtime.h>
#include <cuda_fp16.h>

// KalmanNetNN: 100-step Kalman/GRU scan as per-phase kernels in a CUDA graph.
// Round 8 = Round 7 resubmit (infra failure, never measured):
// drop persistent kernel + spin barriers; 4 small kernels per step,
// kernel boundaries = barriers, each phase ncu-attributable.

#define M10 10
#define NTT 100
#define H1D 1600
#define H2D 400
#define HID 2000
#define G3D 6000
#define DIN 30
#define SW  2048            // uniform padded K stride

// ---------------- device scratch (static; no allocations) ------------------
__device__ __half Wh0h[G3D * SW];
__device__ __half Wh1h[G3D * SW];
__device__ __half Wi1h[G3D * SW];
__device__ __half Wi0h[G3D * SW];
__device__ __half W2h [H2D * SW];
__device__ float  g_W3t[H2D * 128];     // W3 transposed [j][r], r padded to 128
__device__ float  g_W1t[DIN * H1D];     // W1 transposed [k][r]

__device__ float g_ph0[2 * G3D];        // partials: [hf][3H row]
__device__ float g_ph1[2 * G3D];
__device__ float g_pi0[2 * G3D];
__device__ float g_pi1[2 * G3D];
__device__ float g_g[H2D];              // g = relu(W2@h2n + b2), final
__device__ float g_a[H1D];
__device__ float g_h1buf[2][HID];       // double-buffered GRU states
__device__ float g_h2buf[2][HID];
__device__ float g_post[M10], g_prev_post[M10], g_prev_prior[M10], g_yprev[M10];

// ---------------- helpers ---------------------------------------------------
__device__ __forceinline__ float sigmoidf_(float x) {
    return 1.0f / (1.0f + expf(-x));
}
__device__ __forceinline__ float tanhf_(float x) {
    x = fminf(fmaxf(x, -15.0f), 15.0f);
    float e = expf(2.0f * x);
    return (e - 1.0f) / (e + 1.0f);
}
__device__ __forceinline__ float warp_sum(float x) {
#pragma unroll
    for (int o = 16; o; o >>= 1) x += __shfl_xor_sync(0xffffffffu, x, o);
    return x;
}

// 1024-half slice of one row (hf in {0,1}) dotted with fp32 smem vector.
__device__ __forceinline__ float halfrow_dot(const __half* __restrict__ wmat,
                                             int row, int hf,
                                             const float* __restrict__ v,
                                             int lane) {
    const __half* p = wmat + (size_t)row * SW + hf * 1024;
    const float*  q = v + hf * 1024;
    float s = 0.0f;
#pragma unroll
    for (int k = 0; k < 4; k++) {
        int off = k * 256 + lane * 8;
        uint4 wv = *reinterpret_cast<const uint4*>(p + off);
        float4 a0 = *reinterpret_cast<const float4*>(q + off);
        float4 a1 = *reinterpret_cast<const float4*>(q + off + 4);
        const __half2* hp = reinterpret_cast<const __half2*>(&wv);
        float2 f0 = __half22float2(hp[0]);
        float2 f1 = __half22float2(hp[1]);
        float2 f2 = __half22float2(hp[2]);
        float2 f3 = __half22float2(hp[3]);
        s = fmaf(f0.x, a0.x, s); s = fmaf(f0.y, a0.y, s);
        s = fmaf(f1.x, a0.z, s); s = fmaf(f1.y, a0.w, s);
        s = fmaf(f2.x, a1.x, s); s = fmaf(f2.y, a1.y, s);
        s = fmaf(f3.x, a1.z, s); s = fmaf(f3.y, a1.w, s);
    }
#pragma unroll
    for (int o = 16; o; o >>= 1) s += __shfl_xor_sync(0xffffffffu, s, o);
    return s;
}

// ---------------- prep: fp16 convert (vectorized) + transposes + init -------
union U8 { uint4 u; __half2 h[4]; };

__global__ void knet_prep(const float* __restrict__ Wi0,
                          const float* __restrict__ Wh0,
                          const float* __restrict__ Wi1,
                          const float* __restrict__ Wh1,
                          const float* __restrict__ W2,
                          const float* __restrict__ W3,
                          const float* __restrict__ W1,
                          const float* __restrict__ m1x0,
                          const float* __restrict__ F,
                          const float* __restrict__ Hm,
                          const float* __restrict__ h0) {
    const int which = blockIdx.y;
    const unsigned stride = gridDim.x * blockDim.x;
    const unsigned t0 = blockIdx.x * blockDim.x + threadIdx.x;
    if (which < 4) {
        const float* src = (which == 0) ? Wh0 : (which == 1) ? Wh1
                         : (which == 2) ? Wi1 : Wi0;
        __half* dst = (which == 0) ? Wh0h : (which == 1) ? Wh1h
                    : (which == 2) ? Wi1h : Wi0h;
        const int srcK = (which == 3) ? H1D : HID;
        const unsigned ngrp = G3D * (SW / 8);
        for (unsigned i = t0; i < ngrp; i += stride) {
            unsigned c0  = (i & (SW / 8 - 1)) * 8;
            unsigned row = i >> 8;
            U8 u;
            if (c0 < (unsigned)srcK) {
                const float4* s4 = reinterpret_cast<const float4*>(
                    src + (size_t)row * srcK + c0);
                float4 a = s4[0], b = s4[1];
                u.h[0] = __floats2half2_rn(a.x, a.y);
                u.h[1] = __floats2half2_rn(a.z, a.w);
                u.h[2] = __floats2half2_rn(b.x, b.y);
                u.h[3] = __floats2half2_rn(b.z, b.w);
            } else {
                u.u = make_uint4(0, 0, 0, 0);
            }
            *reinterpret_cast<uint4*>(dst + (size_t)row * SW + c0) = u.u;
        }
    } else if (which == 4) {
        const unsigned ngrp = H2D * (SW / 8);
        for (unsigned i = t0; i < ngrp; i += stride) {
            unsigned c0  = (i & (SW / 8 - 1)) * 8;
            unsigned row = i >> 8;
            U8 u;
            if (c0 < HID) {
                const float4* s4 = reinterpret_cast<const float4*>(
                    W2 + (size_t)row * HID + c0);
                float4 a = s4[0], b = s4[1];
                u.h[0] = __floats2half2_rn(a.x, a.y);
                u.h[1] = __floats2half2_rn(a.z, a.w);
                u.h[2] = __floats2half2_rn(b.x, b.y);
                u.h[3] = __floats2half2_rn(b.z, b.w);
            } else {
                u.u = make_uint4(0, 0, 0, 0);
            }
            *reinterpret_cast<uint4*>(W2h + (size_t)row * SW + c0) = u.u;
        }
        for (unsigned i = t0; i < H2D * 128; i += stride) {
            unsigned j = i >> 7, r = i & 127;
            g_W3t[i] = (r < 100) ? W3[r * H2D + j] : 0.0f;
        }
        for (unsigned i = t0; i < DIN * H1D; i += stride) {
            unsigned k = i / H1D, r = i % H1D;
            g_W1t[i] = W1[r * DIN + k];
        }
    } else if (blockIdx.x == 0) {
        int t = threadIdx.x;
        __shared__ float fm[M10];
        if (t < M10) {
            float s = 0.0f;
            for (int j = 0; j < M10; j++) s = fmaf(F[t * M10 + j], m1x0[j], s);
            fm[t] = s;
            g_post[t] = m1x0[t];
            g_prev_post[t] = 0.0f;
            g_prev_prior[t] = m1x0[t];
        }
        __syncthreads();
        if (t < M10) {
            float s = 0.0f;
            for (int j = 0; j < M10; j++) s = fmaf(Hm[t * M10 + j], fm[j], s);
            g_yprev[t] = s;
        }
        for (int i = t; i < HID; i += blockDim.x) {
            g_h1buf[0][i] = h0[i];
            g_h2buf[0][i] = h0[HID + i];
        }
    }
}

// ---------------- block-level epilogue of step te ---------------------------
// s_g: >=400 floats; s_kg: >=128 floats (0..99 KG, 100..109 prior, 112..121 dy)
__device__ void block_epilogue(int te, int tid,
                               const float* __restrict__ y,
                               const float* __restrict__ F,
                               const float* __restrict__ Hm,
                               const float* __restrict__ b3,
                               float* __restrict__ out,
                               float* s_g, float* s_kg) {
    for (int i = tid; i < H2D; i += 256) s_g[i] = g_g[i];   // already relu'd
    __syncthreads();
    if (tid < 128) {
        float a0 = 0, a1 = 0, a2 = 0, a3 = 0;
        for (int j = 0; j < H2D; j += 4) {
            a0 = fmaf(g_W3t[(j    ) * 128 + tid], s_g[j    ], a0);
            a1 = fmaf(g_W3t[(j + 1) * 128 + tid], s_g[j + 1], a1);
            a2 = fmaf(g_W3t[(j + 2) * 128 + tid], s_g[j + 2], a2);
            a3 = fmaf(g_W3t[(j + 3) * 128 + tid], s_g[j + 3], a3);
        }
        float v = a0 + a1 + a2 + a3;
        s_kg[tid] = (tid < 100) ? v + b3[tid] : 0.0f;
    }
    __syncthreads();
    if (tid < 32) {
        int lane = tid;
        if (lane < M10) {
            float s = 0.0f;
            for (int j = 0; j < M10; j++) s = fmaf(F[lane * M10 + j], g_post[j], s);
            s_kg[100 + lane] = s;
        }
        __syncwarp();
        if (lane < M10) {
            float m1y = 0.0f;
            for (int j = 0; j < M10; j++) m1y = fmaf(Hm[lane * M10 + j], s_kg[100 + j], m1y);
            s_kg[112 + lane] = y[lane * NTT + te] - m1y;
        }
        __syncwarp();
        if (lane < M10) {
            float np = s_kg[100 + lane];
            for (int j = 0; j < M10; j++) np = fmaf(s_kg[lane * M10 + j], s_kg[112 + j], np);
            g_prev_post[lane]  = g_post[lane];
            g_prev_prior[lane] = s_kg[100 + lane];
            g_yprev[lane]      = y[lane * NTT + te];
            out[lane * NTT + te] = np;
            g_post[lane] = np;
        }
        __syncwarp();
    }
    __syncthreads();
}

// ---------------- K1: epilogue+features+a (block 0) || Wh dots (blocks 1..) -
__global__ void __launch_bounds__(256)
k_phase1(int t, const float* __restrict__ y, const float* __restrict__ b1,
         const float* __restrict__ b3, const float* __restrict__ F,
         const float* __restrict__ Hm, float* __restrict__ out) {
    __shared__ __align__(16) float s0[SW];
    __shared__ __align__(16) float s1[SW];
    const int tid = threadIdx.x, lane = tid & 31, wid = tid >> 5;
    const int bid = blockIdx.x;
    const int p = t & 1;

    if (bid == 0) {
        float* s_g   = s0;
        float* s_kg  = s0 + 512;
        float* s_kin = s0 + 704;
        if (t > 0) block_epilogue(t - 1, tid, y, F, Hm, b3, out, s_g, s_kg);
        if (tid < 32) {
            float yt = 0, pv = 0, pp = 0, ppr = 0, yp = 0;
            if (lane < M10) {
                yt  = y[lane * NTT + t];
                pv  = g_post[lane];
                pp  = g_prev_post[lane];
                ppr = g_prev_prior[lane];
                yp  = g_yprev[lane];
            }
            float d1 = yt - yp, d3 = pv - pp, d4 = pv - ppr;
            float n1 = fmaxf(sqrtf(warp_sum(d1 * d1)), 1e-12f);
            float n3 = fmaxf(sqrtf(warp_sum(d3 * d3)), 1e-12f);
            float n4 = fmaxf(sqrtf(warp_sum(d4 * d4)), 1e-12f);
            if (lane < M10) {
                s_kin[lane]      = d1 / n1;
                s_kin[10 + lane] = d3 / n3;
                s_kin[20 + lane] = d4 / n4;
            }
        }
        __syncthreads();
        for (int r = tid; r < H1D; r += 256) {
            float s = b1[r];
#pragma unroll
            for (int k = 0; k < DIN; k++)
                s = fmaf(g_W1t[k * H1D + r], s_kin[k], s);
            g_a[r] = fmaxf(s, 0.0f);
        }
        return;
    }

    for (int i = tid; i < SW; i += 256) {
        s0[i] = (i < HID) ? g_h1buf[p][i] : 0.0f;
        s1[i] = (i < HID) ? g_h2buf[p][i] : 0.0f;
    }
    __syncthreads();
    const unsigned gw = (bid - 1) * 8u + (unsigned)wid;
    const unsigned NW = (gridDim.x - 1) * 8u;
    for (unsigned u = gw; u < 24000u; u += NW) {
        bool first = (u < 12000u);
        unsigned v = first ? u : (u - 12000u);
        int row = (int)(v >> 1), hf = (int)(v & 1u);
        float d = first ? halfrow_dot(Wh0h, row, hf, s0, lane)
                        : halfrow_dot(Wh1h, row, hf, s1, lane);
        if (lane == 0) (first ? g_ph0 : g_ph1)[hf * G3D + row] = d;
    }
}

// ---------------- K2: gi0 = Wi0 @ a ----------------------------------------
__global__ void __launch_bounds__(256) k_phase2() {
    __shared__ __align__(16) float s_a[SW];
    const int tid = threadIdx.x, lane = tid & 31, wid = tid >> 5;
    for (int i = tid; i < SW; i += 256) s_a[i] = (i < H1D) ? g_a[i] : 0.0f;
    __syncthreads();
    const unsigned gw = blockIdx.x * 8u + (unsigned)wid;
    const unsigned NW = gridDim.x * 8u;
    for (unsigned u = gw; u < 12000u; u += NW) {
        int row = (int)(u >> 1), hf = (int)(u & 1u);
        float d = halfrow_dot(Wi0h, row, hf, s_a, lane);
        if (lane == 0) g_pi0[hf * G3D + row] = d;
    }
}

// ---------------- K3: h1n combine + gi1 = Wi1 @ h1n ------------------------
__global__ void __launch_bounds__(256)
k_phase3(int t, const float* __restrict__ bi0, const float* __restrict__ bh0) {
    __shared__ __align__(16) float s_h[SW];
    const int tid = threadIdx.x, lane = tid & 31, wid = tid >> 5;
    const int p = t & 1;
    for (int j = tid; j < SW; j += 256) {
        if (j < HID) {
            float ir = bi0[j]           + g_pi0[j]           + g_pi0[G3D + j];
            float iz = bi0[j + HID]     + g_pi0[HID + j]     + g_pi0[G3D + HID + j];
            float in = bi0[j + 2 * HID] + g_pi0[2 * HID + j] + g_pi0[G3D + 2 * HID + j];
            float hr = bh0[j]           + g_ph0[j]           + g_ph0[G3D + j];
            float hz = bh0[j + HID]     + g_ph0[HID + j]     + g_ph0[G3D + HID + j];
            float hn = bh0[j + 2 * HID] + g_ph0[2 * HID + j] + g_ph0[G3D + 2 * HID + j];
            float r  = sigmoidf_(ir + hr);
            float z  = sigmoidf_(iz + hz);
            float nn = tanhf_(in + r * hn);
            float v  = (1.0f - z) * nn + z * g_h1buf[p][j];
            s_h[j] = v;
            if (blockIdx.x == 0) g_h1buf[1 - p][j] = v;
        } else {
            s_h[j] = 0.0f;
        }
    }
    __syncthreads();
    const unsigned gw = blockIdx.x * 8u + (unsigned)wid;
    const unsigned NW = gridDim.x * 8u;
    for (unsigned u = gw; u < 12000u; u += NW) {
        int row = (int)(u >> 1), hf = (int)(u & 1u);
        float d = halfrow_dot(Wi1h, row, hf, s_h, lane);
        if (lane == 0) g_pi1[hf * G3D + row] = d;
    }
}

// ---------------- K4: h2n combine + g = relu(W2 @ h2n + b2) ----------------
__global__ void __launch_bounds__(256)
k_phase4(int t, const float* __restrict__ bi1, const float* __restrict__ bh1,
         const float* __restrict__ b2) {
    __shared__ __align__(16) float s_h[SW];
    const int tid = threadIdx.x, lane = tid & 31, wid = tid >> 5;
    const int p = t & 1;
    for (int j = tid; j < SW; j += 256) {
        if (j < HID) {
            float ir = bi1[j]           + g_pi1[j]           + g_pi1[G3D + j];
            float iz = bi1[j + HID]     + g_pi1[HID + j]     + g_pi1[G3D + HID + j];
            float in = bi1[j + 2 * HID] + g_pi1[2 * HID + j] + g_pi1[G3D + 2 * HID + j];
            float hr = bh1[j]           + g_ph1[j]           + g_ph1[G3D + j];
            float hz = bh1[j + HID]     + g_ph1[HID + j]     + g_ph1[G3D + HID + j];
            float hn = bh1[j + 2 * HID] + g_ph1[2 * HID + j] + g_ph1[G3D + 2 * HID + j];
            float r  = sigmoidf_(ir + hr);
            float z  = sigmoidf_(iz + hz);
            float nn = tanhf_(in + r * hn);
            float v  = (1.0f - z) * nn + z * g_h2buf[p][j];
            s_h[j] = v;
            if (blockIdx.x == 0) g_h2buf[1 - p][j] = v;
        } else {
            s_h[j] = 0.0f;
        }
    }
    __syncthreads();
    const int w = blockIdx.x * 8 + wid;
    if (w < H2D) {
        float d = halfrow_dot(W2h, w, 0, s_h, lane)
                + halfrow_dot(W2h, w, 1, s_h, lane);
        if (lane == 0) g_g[w] = fmaxf(d + b2[w], 0.0f);
    }
}

// ---------------- K5: final epilogue (t = NTT-1) ---------------------------
__global__ void __launch_bounds__(256)
k_final(const float* __restrict__ y, const float* __restrict__ b3,
        const float* __restrict__ F, const float* __restrict__ Hm,
        float* __restrict__ out) {
    __shared__ __align__(16) float s[768];
    block_epilogue(NTT - 1, threadIdx.x, y, F, Hm, b3, out, s, s + 512);
}

// ---------------- launcher --------------------------------------------------
extern "C" void kernel_launch(void* const* d_in, const int* in_sizes, int n_in,
                              void* d_out, int out_size) {
    (void)in_sizes; (void)n_in; (void)out_size;
    const float* y    = (const float*)d_in[0];
    const float* m1x0 = (const float*)d_in[1];
    const float* F    = (const float*)d_in[2];
    const float* Hm   = (const float*)d_in[3];
    const float* h0   = (const float*)d_in[4];
    const float* W1   = (const float*)d_in[5];
    const float* b1   = (const float*)d_in[6];
    const float* Wi0  = (const float*)d_in[7];
    const float* Wh0  = (const float*)d_in[8];
    const float* bi0  = (const float*)d_in[9];
    const float* bh0  = (const float*)d_in[10];
    const float* Wi1  = (const float*)d_in[11];
    const float* Wh1  = (const float*)d_in[12];
    const float* bi1  = (const float*)d_in[13];
    const float* bh1  = (const float*)d_in[14];
    const float* W2   = (const float*)d_in[15];
    const float* b2   = (const float*)d_in[16];
    const float* W3   = (const float*)d_in[17];
    const float* b3   = (const float*)d_in[18];
    float* out = (float*)d_out;

    int dev = 0;
    cudaGetDevice(&dev);
    int nsm = 148;
    cudaDeviceGetAttribute(&nsm, cudaDevAttrMultiProcessorCount, dev);

    knet_prep<<<dim3(4 * nsm, 6), 256>>>(Wi0, Wh0, Wi1, Wh1, W2, W3, W1,
                                         m1x0, F, Hm, h0);
    for (int t = 0; t < NTT; ++t) {
        k_phase1<<<593, 256>>>(t, y, b1, b3, F, Hm, out);
        k_phase2<<<592, 256>>>();
        k_phase3<<<592, 256>>>(t, bi0, bh0);
        k_phase4<<<64, 256>>>(t, bi1, bh1, b2);
    }
    k_final<<<1, 256>>>(y, b3, F, Hm, out);
}